// round 2
// baseline (speedup 1.0000x reference)
#include <cuda_runtime.h>
#include <stdint.h>

// diag(A) @ B : out[i][j] = A[i] * B[i][j]
// N = 8192 rows, M = 8192 cols, fp32. Pure HBM-streaming kernel.
//
// Strategy: 128-bit (float4) grid-stride loop over B. M % 4 == 0 so each
// float4 lies within a single row; row index = (vec_idx * 4) >> 13.
// A (32 KB) stays L1/L2 resident via __ldg.

#ifndef LOG2_M
#define LOG2_M 13  // M = 8192
#endif

__global__ void __launch_bounds__(256) diag_scale_kernel(
    const float* __restrict__ A,
    const float4* __restrict__ B4,
    float4* __restrict__ out4,
    long long n_vec)   // total float4 elements = N*M/4
{
    long long idx = (long long)blockIdx.x * blockDim.x + threadIdx.x;
    long long stride = (long long)gridDim.x * blockDim.x;

    const int vecs_per_row_log2 = LOG2_M - 2;  // 2048 float4 per row

    for (long long v = idx; v < n_vec; v += stride) {
        int row = (int)(v >> vecs_per_row_log2);
        float a = __ldg(&A[row]);
        float4 b = B4[v];
        float4 o;
        o.x = a * b.x;
        o.y = a * b.y;
        o.z = a * b.z;
        o.w = a * b.w;
        out4[v] = o;
    }
}

extern "C" void kernel_launch(void* const* d_in, const int* in_sizes, int n_in,
                              void* d_out, int out_size)
{
    const float* A = (const float*)d_in[0];
    const float4* B4 = (const float4*)d_in[1];
    float4* out4 = (float4*)d_out;

    long long n_elems = (long long)out_size;     // N*M = 67108864
    long long n_vec = n_elems >> 2;              // 16777216 float4

    // Fill the chip: 148 SMs * ~8 resident blocks of 256 threads, with a
    // grid-stride loop giving each thread ~8 float4s (good MLP).
    int threads = 256;
    long long want_blocks = (n_vec + threads - 1) / threads;
    int blocks = (int)((want_blocks + 7) / 8);   // ~8 iterations per thread
    if (blocks > 65535 * 16) blocks = 65535 * 16;
    if (blocks < 1) blocks = 1;

    diag_scale_kernel<<<blocks, threads>>>(A, B4, out4, n_vec);
}

// round 3
// speedup vs baseline: 1.0113x; 1.0113x over previous
#include <cuda_runtime.h>
#include <stdint.h>

// diag(A) @ B : out[i][j] = A[i] * B[i][j]
// N = 8192 rows, M = 8192 cols, fp32. Pure HBM-streaming kernel.
//
// R2: one block == one row. 256 threads x 8 float4 = 2048 float4 = 8192 floats.
// Fully unrolled, loads front-batched (MLP_p1 = 8) for deep L1tex queue,
// streaming cache hints (no reuse across the 512MB working set).

#define THREADS 256
#define UNROLL  8   // 256 * 8 * 4 floats = 8192 = M (one row per block)

__global__ void __launch_bounds__(THREADS) diag_scale_row_kernel(
    const float* __restrict__ A,
    const float4* __restrict__ B4,
    float4* __restrict__ out4)
{
    const int row = blockIdx.x;                       // 8192 blocks = 8192 rows
    const float a = __ldg(&A[row]);

    const long long base = (long long)row * (THREADS * UNROLL) + threadIdx.x;

    // Front-batch all loads: 8 independent LDG.128 in flight per thread.
    float4 b[UNROLL];
#pragma unroll
    for (int k = 0; k < UNROLL; k++) {
        b[k] = __ldcs(&B4[base + (long long)k * THREADS]);
    }

#pragma unroll
    for (int k = 0; k < UNROLL; k++) {
        float4 o;
        o.x = a * b[k].x;
        o.y = a * b[k].y;
        o.z = a * b[k].z;
        o.w = a * b[k].w;
        __stcs(&out4[base + (long long)k * THREADS], o);
    }
}

extern "C" void kernel_launch(void* const* d_in, const int* in_sizes, int n_in,
                              void* d_out, int out_size)
{
    const float* A = (const float*)d_in[0];
    const float4* B4 = (const float4*)d_in[1];
    float4* out4 = (float4*)d_out;

    // N rows = out_size / M; M = 8192. One block per row.
    int n_rows = (int)((long long)out_size / 8192);

    diag_scale_row_kernel<<<n_rows, THREADS>>>(A, B4, out4);
}